// round 8
// baseline (speedup 1.0000x reference)
#include <cuda_runtime.h>
#include <cuda_bf16.h>
#include <cstdint>
#include <cstddef>

#define B_   512
#define T_   2048
#define NP   800          // C*M pairs
#define TPB  512
#define NBLK 128          // B_/4, 4 batches per block

#define L2E     1.4426950408889634f
#define TWO_L2E 2.8853900817779268f

// ---- shared layout (float offsets) ----
#define OFF_SQ   0        // Sq[4 quad][800][4] : S quads transposed, *2*log2e (12800 f)
#define OFF_AT   12800    // float at[16][804]  : A transposed (PERMUTED q)    (12864 f)
#define OFF_UK   25664    // float4 uk[400]     : (u2,k)[dp], (u2,k)[dp+400]   ( 1600 f)
#define OFF_W    27264    // float w[4][816]    : permuted q, stride 816       ( 3264 f)
#define OFF_RED  30528    // float red[4][16][16]                              ( 1024 f)
#define OFF_ST   31552    // float st[4][20]                                   (   80 f)
#define OFF_GATE 31632    // float gate[2][4][8]                               (   64 f)
#define OFF_XB   31696    // float xb[2][4]                                    (    8 f)
#define SMEM_FLOATS 31704
#define SMEM_BYTES  (SMEM_FLOATS * 4)

typedef unsigned long long u64;

__device__ float g_gate[(size_t)B_ * T_ * 8];

__device__ __forceinline__ float ex2f(float a)
{
    float r;
    asm("ex2.approx.ftz.f32 %0, %1;" : "=f"(r) : "f"(a));
    return r;
}
__device__ __forceinline__ u64 fma2(u64 b, u64 c, u64 a)   // b*c + a
{
    u64 d;
    asm("fma.rn.f32x2 %0, %1, %2, %3;" : "=l"(d) : "l"(b), "l"(c), "l"(a));
    return d;
}
__device__ __forceinline__ u64 mul2(u64 a, u64 b)
{
    u64 d;
    asm("mul.rn.f32x2 %0, %1, %2;" : "=l"(d) : "l"(a), "l"(b));
    return d;
}
__device__ __forceinline__ float2 upk(u64 a)
{
    float2 f;
    asm("mov.b64 {%0, %1}, %2;" : "=f"(f.x), "=f"(f.y) : "l"(a));
    return f;
}
__device__ __forceinline__ u64 pk2(float lo, float hi)
{
    u64 d;
    asm("mov.b64 %0, {%1, %2};" : "=l"(d) : "f"(lo), "f"(hi));
    return d;
}

// ---------------------------------------------------------------------------
// Kernel 1: gate[b,t,:] = softmax(relu(x*W1+b1) @ W2 + b2). One thread per (b,t).
// ---------------------------------------------------------------------------
__global__ void gate_kernel(const float* __restrict__ x,
                            const float* __restrict__ W1,
                            const float* __restrict__ b1,
                            const float* __restrict__ W2,
                            const float* __restrict__ b2)
{
    int idx = blockIdx.x * blockDim.x + threadIdx.x;
    if (idx >= B_ * T_) return;
    float xv = x[idx];

    float lg[8];
#pragma unroll
    for (int c = 0; c < 8; c++) lg[c] = __ldg(&b2[c]);
#pragma unroll
    for (int jj = 0; jj < 16; jj++) {
        float h = fmaxf(fmaf(xv, __ldg(&W1[jj]), __ldg(&b1[jj])), 0.0f);
#pragma unroll
        for (int c = 0; c < 8; c++)
            lg[c] = fmaf(h, __ldg(&W2[jj * 8 + c]), lg[c]);
    }
    float m = lg[0];
#pragma unroll
    for (int c = 1; c < 8; c++) m = fmaxf(m, lg[c]);
    float e[8], ssum = 0.0f;
#pragma unroll
    for (int c = 0; c < 8; c++) { e[c] = __expf(lg[c] - m); ssum += e[c]; }
    float inv = 1.0f / ssum;
#pragma unroll
    for (int c = 0; c < 8; c++) g_gate[(size_t)idx * 8 + c] = e[c] * inv;
}

// ---------------------------------------------------------------------------
// Kernel 2: recurrent scan. 128 blocks x 512 threads, 4 batches per block.
// Phase A thread (b,pp) handles pair HALVES (dp, dp+400): S loads are
// 128B-contiguous per warp (conflict-free), uk is one LDS.128, W one STS.64
// into the permuted slot q = 2*dp+half (A^T staged with same permutation).
// Phase B (nn,j) with A register-cached. 256-thread final reduce.
// ---------------------------------------------------------------------------
__global__ void __launch_bounds__(TPB, 1)
scan_kernel(const float* __restrict__ x,
            const float* __restrict__ S,
            const float* __restrict__ U,
            const float* __restrict__ A,
            float* __restrict__ out)
{
    extern __shared__ float sm[];
    const int tid = threadIdx.x;
    const int b0  = blockIdx.x * 4;

    // ---------------- stage S', A^T (permuted), (u2, k') ----------------
    for (int idx = tid; idx < NP * 16; idx += TPB) {
        int p = idx >> 4, k = idx & 15;
        sm[OFF_SQ + (k >> 2) * 3200 + (p << 2) + (k & 3)] = TWO_L2E * S[idx];
        int q = (p < 400) ? 2 * p : 2 * (p - 400) + 1;    // half-interleave perm
        sm[OFF_AT + k * 804 + q] = A[idx];
    }
    for (int p = tid; p < NP; p += TPB) {
        float acc = 0.0f;
#pragma unroll
        for (int k = 0; k < 16; k++) { float v = S[p * 16 + k]; acc = fmaf(v, v, acc); }
        float uv = U[p];
        int  dp = (p < 400) ? p : p - 400;
        int  h  = (p < 400) ? 0 : 1;
        sm[OFF_UK + 4 * dp + 2 * h]     = TWO_L2E * uv;
        sm[OFF_UK + 4 * dp + 2 * h + 1] = L2E * fmaf(uv, uv, acc);
    }
    if (tid < 32) {
        sm[OFF_GATE + tid] = g_gate[((size_t)(b0 + (tid >> 3)) * T_) * 8 + (tid & 7)];
        if (tid < 4) sm[OFF_XB + tid] = x[(size_t)(b0 + tid) * T_];
    }
    __syncthreads();

    const int b    = tid & 3;    // phase A batch
    const int pp   = tid >> 2;   // phase A dpair lane (0..127)
    const int nn   = tid & 15;   // phase B output dim
    const int j    = tid >> 4;   // phase B chunk lane (0..31)
    const int lane = tid & 31;
    const int wrp  = tid >> 5;

    const ulonglong2* Sq2 = (const ulonglong2*)(sm + OFF_SQ);
    const ulonglong2* At2 = (const ulonglong2*)(sm + OFF_AT + nn * 804);
    const ulonglong2* Wb2 = (const ulonglong2*)(sm + OFF_W);

    // -------- A register cache: 6 chunks per thread, static across t --------
    ulonglong2 Ac[6];
#pragma unroll
    for (int i = 0; i < 6; i++) Ac[i] = At2[j + 32 * i];

    // packed state (8 x f32x2); xv = raw x_t; hs = (-h', 0) dot seed
    u64 s0 = 0, s1 = 0, s2 = 0, s3 = 0, s4 = 0, s5 = 0, s6 = 0, s7 = 0;
    float xv = sm[OFF_XB + b];
    u64 hs = pk2(-L2E * xv * xv, 0.0f);

    for (int t = 0; t < T_; t++) {
        const int par = t & 1;

        // next-step gate/x loads (committed after bar1, consumed at step end)
        float gpre = 0.f, xpre = 0.f;
        const bool pf = (tid < 32) && (t + 1 < T_);
        if (pf) {
            gpre = g_gate[((size_t)(b0 + (tid >> 3)) * T_ + (t + 1)) * 8 + (tid & 7)];
            if (tid < 4) xpre = x[(size_t)(b0 + tid) * T_ + (t + 1)];
        }

        // ---------------- phase A: pairs (dp, dp+400) ----------------
        {
            const float* gsh = sm + OFF_GATE + par * 32 + b * 8;

            auto dpair = [&](int dp, int ci) {
                ulonglong2 q0a = Sq2[dp],         q0b = Sq2[400 + dp];
                ulonglong2 q1a = Sq2[800 + dp],   q1b = Sq2[1200 + dp];
                ulonglong2 q2a = Sq2[1600 + dp],  q2b = Sq2[2000 + dp];
                ulonglong2 q3a = Sq2[2400 + dp],  q3b = Sq2[2800 + dp];
                float4 uk4 = *(const float4*)(sm + OFF_UK + 4 * dp);
                float ga = gsh[ci], gb = gsh[ci + 4];

                u64 da = fma2(q0a.x, s0, hs);
                da = fma2(q0a.y, s1, da);
                da = fma2(q1a.x, s2, da);
                da = fma2(q1a.y, s3, da);
                u64 db = mul2(q2a.x, s4);
                db = fma2(q2a.y, s5, db);
                db = fma2(q3a.x, s6, db);
                db = fma2(q3a.y, s7, db);
                float2 fa = upk(da), fb = upk(db);
                float e0 = fmaf(xv, uk4.x, (fa.x + fa.y) + (fb.x + fb.y)) - uk4.y;

                u64 dc = fma2(q0b.x, s0, hs);
                dc = fma2(q0b.y, s1, dc);
                dc = fma2(q1b.x, s2, dc);
                dc = fma2(q1b.y, s3, dc);
                u64 dd = mul2(q2b.x, s4);
                dd = fma2(q2b.y, s5, dd);
                dd = fma2(q3b.x, s6, dd);
                dd = fma2(q3b.y, s7, dd);
                float2 fc = upk(dc), fd = upk(dd);
                float e1 = fmaf(xv, uk4.z, (fc.x + fc.y) + (fd.x + fd.y)) - uk4.w;

                *(float2*)(sm + OFF_W + b * 816 + 2 * dp) =
                    make_float2(ga * ex2f(e0), gb * ex2f(e1));
            };
#pragma unroll
            for (int i = 0; i < 3; i++) {
                int dp = pp + 128 * i;
                dpair(dp, (unsigned)dp / 100u);
            }
            if (pp >= 112) dpair(272 + pp, 3);   // dp 384..399: cells 3 / 7
        }
        __syncthreads();                             // bar 1

        // commit prefetched gate/x for t+1
        if (pf) {
            sm[OFF_GATE + (par ^ 1) * 32 + tid] = gpre;
            if (tid < 4) sm[OFF_XB + (par ^ 1) * 4 + tid] = xpre;
        }

        // ---------------- phase B: s_new[b][n] = sum_q w[b][q]*A[q][n] -------
        u64 c0 = 0, c1 = 0, c2 = 0, c3 = 0;
        auto chunkB = [&](int p4, ulonglong2 av) {
            ulonglong2 w0 = Wb2[p4];
            ulonglong2 w1 = Wb2[204 + p4];
            ulonglong2 w2 = Wb2[408 + p4];
            ulonglong2 w3 = Wb2[612 + p4];
            c0 = fma2(av.x, w0.x, c0); c0 = fma2(av.y, w0.y, c0);
            c1 = fma2(av.x, w1.x, c1); c1 = fma2(av.y, w1.y, c1);
            c2 = fma2(av.x, w2.x, c2); c2 = fma2(av.y, w2.y, c2);
            c3 = fma2(av.x, w3.x, c3); c3 = fma2(av.y, w3.y, c3);
        };
#pragma unroll
        for (int i = 0; i < 6; i++) chunkB(j + 32 * i, Ac[i]);
        if (j >= 24) chunkB(168 + j, At2[168 + j]);  // tail chunks 192..199

        float2 f0 = upk(c0), f1 = upk(c1), f2 = upk(c2), f3 = upk(c3);
        float a0 = f0.x + f0.y, a1 = f1.x + f1.y, a2 = f2.x + f2.y, a3 = f3.x + f3.y;
        a0 += __shfl_xor_sync(0xffffffffu, a0, 16);
        a1 += __shfl_xor_sync(0xffffffffu, a1, 16);
        a2 += __shfl_xor_sync(0xffffffffu, a2, 16);
        a3 += __shfl_xor_sync(0xffffffffu, a3, 16);
        if (lane < 16) {
            sm[OFF_RED +       wrp * 16 + lane] = a0;
            sm[OFF_RED + 256 + wrp * 16 + lane] = a1;
            sm[OFF_RED + 512 + wrp * 16 + lane] = a2;
            sm[OFF_RED + 768 + wrp * 16 + lane] = a3;
        }
        __syncthreads();                             // bar 2

        // ---------------- final reduce + output (256 threads, 4+shfl) --------
        if (tid < 256) {
            const int bb = tid >> 6, n2 = (tid >> 2) & 15, g = tid & 3;
            const float* r = sm + OFF_RED + bb * 256 + g * 16 + n2;
            float v = (r[0] + r[64]) + (r[128] + r[192]);   // warps g, g+4, g+8, g+12
            v += __shfl_xor_sync(0xffffffffu, v, 1);
            v += __shfl_xor_sync(0xffffffffu, v, 2);
            if (g == 0) {
                sm[OFF_ST + bb * 20 + n2] = v;
                if (n2 == 15) out[(size_t)(b0 + bb) * T_ + t] = v;
            }
        }
        __syncthreads();                             // bar 3

        // reload packed state; recompute h' locally
        {
            const ulonglong2* st2 = (const ulonglong2*)(sm + OFF_ST + b * 20);
            ulonglong2 u0 = st2[0], u1 = st2[1], u2 = st2[2], u3 = st2[3];
            s0 = u0.x; s1 = u0.y; s2 = u1.x; s3 = u1.y;
            s4 = u2.x; s5 = u2.y; s6 = u3.x; s7 = u3.y;
            xv = sm[OFF_XB + (par ^ 1) * 4 + b];
            u64 acc = mul2(s0, s0);
            acc = fma2(s1, s1, acc);
            acc = fma2(s2, s2, acc);
            acc = fma2(s3, s3, acc);
            acc = fma2(s4, s4, acc);
            acc = fma2(s5, s5, acc);
            acc = fma2(s6, s6, acc);
            acc = fma2(s7, s7, acc);
            float2 fs = upk(acc);
            float hv = fmaf(xv, xv, fs.x + fs.y);
            hs = pk2(-L2E * hv, 0.0f);
        }
    }
}

// ---------------------------------------------------------------------------
extern "C" void kernel_launch(void* const* d_in, const int* in_sizes, int n_in,
                              void* d_out, int out_size)
{
    const float* x  = (const float*)d_in[0];
    const float* S  = (const float*)d_in[1];
    const float* U  = (const float*)d_in[2];
    const float* A  = (const float*)d_in[3];
    const float* W1 = (const float*)d_in[4];
    const float* b1 = (const float*)d_in[5];
    const float* W2 = (const float*)d_in[6];
    const float* b2 = (const float*)d_in[7];
    float* out = (float*)d_out;

    cudaFuncSetAttribute(scan_kernel,
                         cudaFuncAttributeMaxDynamicSharedMemorySize, SMEM_BYTES);

    gate_kernel<<<(B_ * T_ + 255) / 256, 256>>>(x, W1, b1, W2, b2);
    scan_kernel<<<NBLK, TPB, SMEM_BYTES>>>(x, S, U, A, out);
}

// round 9
// speedup vs baseline: 1.0404x; 1.0404x over previous
#include <cuda_runtime.h>
#include <cuda_bf16.h>
#include <cstdint>
#include <cstddef>

#define B_   512
#define T_   2048
#define NP   800          // C*M pairs
#define TPB  512
#define NBLK 128          // B_/4, 4 batches per block

#define L2E     1.4426950408889634f
#define TWO_L2E 2.8853900817779268f

// ---- shared layout (float offsets) ----
#define OFF_SQ   0        // Sq planes[8][400][4]: plane = quad*2+(p&1), elem p>>1 (12800 f)
#define OFF_AT   12800    // float at[16][804]  : A transposed, padded         (12864 f)
#define OFF_UK   25664    // float2 uk[800]     : (2*l2e*U, l2e*(|S|^2+U^2))   ( 1600 f)
#define OFF_W    27264    // float w[4][808]    : stride 808 -> conflict-free  ( 3232 f)
#define OFF_RED  30496    // float red[4][16][16]                              ( 1024 f)
#define OFF_ST   31520    // float st[4][20]                                   (   80 f)
#define OFF_GATE 31600    // float gate[2][4][8]                               (   64 f)
#define OFF_XB   31664    // float xb[2][4]                                    (    8 f)
#define SMEM_FLOATS 31672
#define SMEM_BYTES  (SMEM_FLOATS * 4)

typedef unsigned long long u64;

__device__ float g_gate[(size_t)B_ * T_ * 8];

__device__ __forceinline__ float ex2f(float a)
{
    float r;
    asm("ex2.approx.ftz.f32 %0, %1;" : "=f"(r) : "f"(a));
    return r;
}
__device__ __forceinline__ u64 fma2(u64 b, u64 c, u64 a)   // b*c + a
{
    u64 d;
    asm("fma.rn.f32x2 %0, %1, %2, %3;" : "=l"(d) : "l"(b), "l"(c), "l"(a));
    return d;
}
__device__ __forceinline__ u64 mul2(u64 a, u64 b)
{
    u64 d;
    asm("mul.rn.f32x2 %0, %1, %2;" : "=l"(d) : "l"(a), "l"(b));
    return d;
}
__device__ __forceinline__ float2 upk(u64 a)
{
    float2 f;
    asm("mov.b64 {%0, %1}, %2;" : "=f"(f.x), "=f"(f.y) : "l"(a));
    return f;
}
__device__ __forceinline__ u64 pk2(float lo, float hi)
{
    u64 d;
    asm("mov.b64 %0, {%1, %2};" : "=l"(d) : "f"(lo), "f"(hi));
    return d;
}

// ---------------------------------------------------------------------------
// Kernel 1: gate[b,t,:] = softmax(relu(x*W1+b1) @ W2 + b2). One thread per (b,t).
// ---------------------------------------------------------------------------
__global__ void gate_kernel(const float* __restrict__ x,
                            const float* __restrict__ W1,
                            const float* __restrict__ b1,
                            const float* __restrict__ W2,
                            const float* __restrict__ b2)
{
    int idx = blockIdx.x * blockDim.x + threadIdx.x;
    if (idx >= B_ * T_) return;
    float xv = x[idx];

    float lg[8];
#pragma unroll
    for (int c = 0; c < 8; c++) lg[c] = __ldg(&b2[c]);
#pragma unroll
    for (int jj = 0; jj < 16; jj++) {
        float h = fmaxf(fmaf(xv, __ldg(&W1[jj]), __ldg(&b1[jj])), 0.0f);
#pragma unroll
        for (int c = 0; c < 8; c++)
            lg[c] = fmaf(h, __ldg(&W2[jj * 8 + c]), lg[c]);
    }
    float m = lg[0];
#pragma unroll
    for (int c = 1; c < 8; c++) m = fmaxf(m, lg[c]);
    float e[8], ssum = 0.0f;
#pragma unroll
    for (int c = 0; c < 8; c++) { e[c] = __expf(lg[c] - m); ssum += e[c]; }
    float inv = 1.0f / ssum;
#pragma unroll
    for (int c = 0; c < 8; c++) g_gate[(size_t)idx * 8 + c] = e[c] * inv;
}

// ---------------------------------------------------------------------------
// Kernel 2: recurrent scan. 128 blocks x 512 threads, 4 batches per block.
// Identical to the 3063us kernel EXCEPT the Sq shared layout: S quads are
// stored in 8 planes (plane = quad*2 + (p&1), elem p>>1) so the 8 per-dpair
// loads Sq2[plane*400+dp] are warp-contiguous 128B (conflict-free), while the
// dpair still covers adjacent pairs (2dp, 2dp+1) sharing one cell/gate.
// ---------------------------------------------------------------------------
__global__ void __launch_bounds__(TPB, 1)
scan_kernel(const float* __restrict__ x,
            const float* __restrict__ S,
            const float* __restrict__ U,
            const float* __restrict__ A,
            float* __restrict__ out)
{
    extern __shared__ float sm[];
    const int tid = threadIdx.x;
    const int b0  = blockIdx.x * 4;

    // ---------------- stage S' (plane layout), A^T, (u2, k') ----------------
    for (int idx = tid; idx < NP * 16; idx += TPB) {
        int p = idx >> 4, k = idx & 15;
        int plane = (k >> 2) * 2 + (p & 1);
        sm[OFF_SQ + plane * 1600 + (p >> 1) * 4 + (k & 3)] = TWO_L2E * S[idx];
        sm[OFF_AT + k * 804 + p] = A[idx];
    }
    for (int p = tid; p < NP; p += TPB) {
        float acc = 0.0f;
#pragma unroll
        for (int k = 0; k < 16; k++) { float v = S[p * 16 + k]; acc = fmaf(v, v, acc); }
        float uv = U[p];
        sm[OFF_UK + 2 * p]     = TWO_L2E * uv;
        sm[OFF_UK + 2 * p + 1] = L2E * fmaf(uv, uv, acc);
    }
    if (tid < 32) {
        sm[OFF_GATE + tid] = g_gate[((size_t)(b0 + (tid >> 3)) * T_) * 8 + (tid & 7)];
        if (tid < 4) sm[OFF_XB + tid] = x[(size_t)(b0 + tid) * T_];
    }
    __syncthreads();

    const int b    = tid & 3;    // phase A batch
    const int pp   = tid >> 2;   // phase A dpair lane (0..127)
    const int nn   = tid & 15;   // phase B output dim
    const int j    = tid >> 4;   // phase B chunk lane (0..31)
    const int lane = tid & 31;
    const int wrp  = tid >> 5;

    const ulonglong2* Sq2 = (const ulonglong2*)(sm + OFF_SQ);
    const ulonglong2* At2 = (const ulonglong2*)(sm + OFF_AT + nn * 804);
    const ulonglong2* Wb2 = (const ulonglong2*)(sm + OFF_W);

    // -------- A register cache: 6 chunks per thread, static across t --------
    ulonglong2 Ac[6];
#pragma unroll
    for (int i = 0; i < 6; i++) Ac[i] = At2[j + 32 * i];

    // packed state (8 x f32x2); xv = raw x_t; hs = (-h', 0) dot seed
    u64 s0 = 0, s1 = 0, s2 = 0, s3 = 0, s4 = 0, s5 = 0, s6 = 0, s7 = 0;
    float xv = sm[OFF_XB + b];
    u64 hs = pk2(-L2E * xv * xv, 0.0f);

    for (int t = 0; t < T_; t++) {
        const int par = t & 1;

        // next-step gate/x loads (committed after bar1, consumed at step end)
        float gpre = 0.f, xpre = 0.f;
        const bool pf = (tid < 32) && (t + 1 < T_);
        if (pf) {
            gpre = g_gate[((size_t)(b0 + (tid >> 3)) * T_ + (t + 1)) * 8 + (tid & 7)];
            if (tid < 4) xpre = x[(size_t)(b0 + tid) * T_ + (t + 1)];
        }

        // ---------------- phase A: pairs (2dp, 2dp+1) via plane loads --------
        {
            const float* gsh = sm + OFF_GATE + par * 32 + b * 8;

            auto dpair = [&](int dp, int ci) {
                ulonglong2 q0a = Sq2[dp],         q0b = Sq2[400 + dp];
                ulonglong2 q1a = Sq2[800 + dp],   q1b = Sq2[1200 + dp];
                ulonglong2 q2a = Sq2[1600 + dp],  q2b = Sq2[2000 + dp];
                ulonglong2 q3a = Sq2[2400 + dp],  q3b = Sq2[2800 + dp];
                float4 uk4 = *(const float4*)(sm + OFF_UK + 4 * dp);
                float g = gsh[ci];

                u64 da = fma2(q0a.x, s0, hs);
                da = fma2(q0a.y, s1, da);
                da = fma2(q1a.x, s2, da);
                da = fma2(q1a.y, s3, da);
                u64 db = mul2(q2a.x, s4);
                db = fma2(q2a.y, s5, db);
                db = fma2(q3a.x, s6, db);
                db = fma2(q3a.y, s7, db);
                float2 fa = upk(da), fb = upk(db);
                float e0 = fmaf(xv, uk4.x, (fa.x + fa.y) + (fb.x + fb.y)) - uk4.y;

                u64 dc = fma2(q0b.x, s0, hs);
                dc = fma2(q0b.y, s1, dc);
                dc = fma2(q1b.x, s2, dc);
                dc = fma2(q1b.y, s3, dc);
                u64 dd = mul2(q2b.x, s4);
                dd = fma2(q2b.y, s5, dd);
                dd = fma2(q3b.x, s6, dd);
                dd = fma2(q3b.y, s7, dd);
                float2 fc = upk(dc), fd = upk(dd);
                float e1 = fmaf(xv, uk4.z, (fc.x + fc.y) + (fd.x + fd.y)) - uk4.w;

                *(float2*)(sm + OFF_W + b * 808 + 2 * dp) =
                    make_float2(g * ex2f(e0), g * ex2f(e1));
            };
#pragma unroll
            for (int i = 0; i < 3; i++) {
                int dp = pp + 128 * i;
                dpair(dp, (unsigned)dp / 50u);
            }
            if (pp >= 112) dpair(272 + pp, 7);   // dp 384..399 -> pairs 768..799
        }
        __syncthreads();                             // bar 1

        // commit prefetched gate/x for t+1
        if (pf) {
            sm[OFF_GATE + (par ^ 1) * 32 + tid] = gpre;
            if (tid < 4) sm[OFF_XB + (par ^ 1) * 4 + tid] = xpre;
        }

        // ---------------- phase B: s_new[b][n] = sum_p w[b][p]*A[p][n] -------
        u64 c0 = 0, c1 = 0, c2 = 0, c3 = 0;
        auto chunkB = [&](int p4, ulonglong2 av) {
            ulonglong2 w0 = Wb2[p4];
            ulonglong2 w1 = Wb2[202 + p4];
            ulonglong2 w2 = Wb2[404 + p4];
            ulonglong2 w3 = Wb2[606 + p4];
            c0 = fma2(av.x, w0.x, c0); c0 = fma2(av.y, w0.y, c0);
            c1 = fma2(av.x, w1.x, c1); c1 = fma2(av.y, w1.y, c1);
            c2 = fma2(av.x, w2.x, c2); c2 = fma2(av.y, w2.y, c2);
            c3 = fma2(av.x, w3.x, c3); c3 = fma2(av.y, w3.y, c3);
        };
#pragma unroll
        for (int i = 0; i < 6; i++) chunkB(j + 32 * i, Ac[i]);
        if (j >= 24) chunkB(168 + j, At2[168 + j]);  // tail chunks 192..199

        float2 f0 = upk(c0), f1 = upk(c1), f2 = upk(c2), f3 = upk(c3);
        float a0 = f0.x + f0.y, a1 = f1.x + f1.y, a2 = f2.x + f2.y, a3 = f3.x + f3.y;
        a0 += __shfl_xor_sync(0xffffffffu, a0, 16);
        a1 += __shfl_xor_sync(0xffffffffu, a1, 16);
        a2 += __shfl_xor_sync(0xffffffffu, a2, 16);
        a3 += __shfl_xor_sync(0xffffffffu, a3, 16);
        if (lane < 16) {
            sm[OFF_RED +       wrp * 16 + lane] = a0;
            sm[OFF_RED + 256 + wrp * 16 + lane] = a1;
            sm[OFF_RED + 512 + wrp * 16 + lane] = a2;
            sm[OFF_RED + 768 + wrp * 16 + lane] = a3;
        }
        __syncthreads();                             // bar 2

        // ---------------- final reduce + output (256 threads, 4+shfl) --------
        if (tid < 256) {
            const int bb = tid >> 6, n2 = (tid >> 2) & 15, g = tid & 3;
            const float* r = sm + OFF_RED + bb * 256 + g * 16 + n2;
            float v = (r[0] + r[64]) + (r[128] + r[192]);   // warps g, g+4, g+8, g+12
            v += __shfl_xor_sync(0xffffffffu, v, 1);
            v += __shfl_xor_sync(0xffffffffu, v, 2);
            if (g == 0) {
                sm[OFF_ST + bb * 20 + n2] = v;
                if (n2 == 15) out[(size_t)(b0 + bb) * T_ + t] = v;
            }
        }
        __syncthreads();                             // bar 3

        // reload packed state; recompute h' locally
        {
            const ulonglong2* st2 = (const ulonglong2*)(sm + OFF_ST + b * 20);
            ulonglong2 u0 = st2[0], u1 = st2[1], u2 = st2[2], u3 = st2[3];
            s0 = u0.x; s1 = u0.y; s2 = u1.x; s3 = u1.y;
            s4 = u2.x; s5 = u2.y; s6 = u3.x; s7 = u3.y;
            xv = sm[OFF_XB + (par ^ 1) * 4 + b];
            u64 acc = mul2(s0, s0);
            acc = fma2(s1, s1, acc);
            acc = fma2(s2, s2, acc);
            acc = fma2(s3, s3, acc);
            acc = fma2(s4, s4, acc);
            acc = fma2(s5, s5, acc);
            acc = fma2(s6, s6, acc);
            acc = fma2(s7, s7, acc);
            float2 fs = upk(acc);
            float hv = fmaf(xv, xv, fs.x + fs.y);
            hs = pk2(-L2E * hv, 0.0f);
        }
    }
}

// ---------------------------------------------------------------------------
extern "C" void kernel_launch(void* const* d_in, const int* in_sizes, int n_in,
                              void* d_out, int out_size)
{
    const float* x  = (const float*)d_in[0];
    const float* S  = (const float*)d_in[1];
    const float* U  = (const float*)d_in[2];
    const float* A  = (const float*)d_in[3];
    const float* W1 = (const float*)d_in[4];
    const float* b1 = (const float*)d_in[5];
    const float* W2 = (const float*)d_in[6];
    const float* b2 = (const float*)d_in[7];
    float* out = (float*)d_out;

    cudaFuncSetAttribute(scan_kernel,
                         cudaFuncAttributeMaxDynamicSharedMemorySize, SMEM_BYTES);

    gate_kernel<<<(B_ * T_ + 255) / 256, 256>>>(x, W1, b1, W2, b2);
    scan_kernel<<<NBLK, TPB, SMEM_BYTES>>>(x, S, U, A, out);
}

// round 10
// speedup vs baseline: 1.0463x; 1.0057x over previous
#include <cuda_runtime.h>
#include <cuda_bf16.h>
#include <cstdint>
#include <cstddef>

#define B_   512
#define T_   2048
#define NP   800          // C*M pairs
#define TPB  512
#define NBLK 128          // B_/4, 4 batches per block

#define L2E     1.4426950408889634f
#define TWO_L2E 2.8853900817779268f

// ---- shared layout (float offsets) ----
#define OFF_SQ   0        // Sq[4 quad][800][4] : S quads transposed, *2*log2e (12800 f)
#define OFF_AT   12800    // float at[16][804]  : A transposed, padded         (12864 f)
#define OFF_UK   25664    // float2 uk[800]     : (2*l2e*U, l2e*(|S|^2+U^2))   ( 1600 f)
#define OFF_W    27264    // float w[4][808]    : stride 808 -> conflict-free  ( 3232 f)
#define OFF_RED  30496    // float red[4][16][16]                              ( 1024 f)
#define OFF_ST   31520    // float st[4][20]                                   (   80 f)
#define OFF_GATE 31600    // float gate[2][4][8]                               (   64 f)
#define OFF_XB   31664    // float xb[2][4]                                    (    8 f)
#define SMEM_FLOATS 31672
#define SMEM_BYTES  (SMEM_FLOATS * 4)

typedef unsigned long long u64;

__device__ float g_gate[(size_t)B_ * T_ * 8];

__device__ __forceinline__ float ex2f(float a)
{
    float r;
    asm("ex2.approx.ftz.f32 %0, %1;" : "=f"(r) : "f"(a));
    return r;
}
__device__ __forceinline__ u64 fma2(u64 b, u64 c, u64 a)   // b*c + a
{
    u64 d;
    asm("fma.rn.f32x2 %0, %1, %2, %3;" : "=l"(d) : "l"(b), "l"(c), "l"(a));
    return d;
}
__device__ __forceinline__ u64 mul2(u64 a, u64 b)
{
    u64 d;
    asm("mul.rn.f32x2 %0, %1, %2;" : "=l"(d) : "l"(a), "l"(b));
    return d;
}
__device__ __forceinline__ float2 upk(u64 a)
{
    float2 f;
    asm("mov.b64 {%0, %1}, %2;" : "=f"(f.x), "=f"(f.y) : "l"(a));
    return f;
}
__device__ __forceinline__ u64 pk2(float lo, float hi)
{
    u64 d;
    asm("mov.b64 %0, {%1, %2};" : "=l"(d) : "f"(lo), "f"(hi));
    return d;
}

// ---------------------------------------------------------------------------
// Kernel 1: gate[b,t,:] = softmax(relu(x*W1+b1) @ W2 + b2). One thread per (b,t).
// ---------------------------------------------------------------------------
__global__ void gate_kernel(const float* __restrict__ x,
                            const float* __restrict__ W1,
                            const float* __restrict__ b1,
                            const float* __restrict__ W2,
                            const float* __restrict__ b2)
{
    int idx = blockIdx.x * blockDim.x + threadIdx.x;
    if (idx >= B_ * T_) return;
    float xv = x[idx];

    float lg[8];
#pragma unroll
    for (int c = 0; c < 8; c++) lg[c] = __ldg(&b2[c]);
#pragma unroll
    for (int jj = 0; jj < 16; jj++) {
        float h = fmaxf(fmaf(xv, __ldg(&W1[jj]), __ldg(&b1[jj])), 0.0f);
#pragma unroll
        for (int c = 0; c < 8; c++)
            lg[c] = fmaf(h, __ldg(&W2[jj * 8 + c]), lg[c]);
    }
    float m = lg[0];
#pragma unroll
    for (int c = 1; c < 8; c++) m = fmaxf(m, lg[c]);
    float e[8], ssum = 0.0f;
#pragma unroll
    for (int c = 0; c < 8; c++) { e[c] = __expf(lg[c] - m); ssum += e[c]; }
    float inv = 1.0f / ssum;
#pragma unroll
    for (int c = 0; c < 8; c++) g_gate[(size_t)idx * 8 + c] = e[c] * inv;
}

// ---------------------------------------------------------------------------
// Kernel 2: recurrent scan. 128 blocks x 512 threads, 4 batches per block.
// R6 base + critical-warp balancing:
//   phase A: 3 dpairs on all lanes; pairs 768..799 as 32 SINGLE pairs on
//            lanes pp>=96 (critical warp 4.0 -> 3.5 dpair-equiv).
//   phase B: 6 chunks on all j; chunks 192..199 as 16 HALF-chunks on j<16
//            (warps 0-7; critical warp 7 -> 6.5 chunks, off the A-tail warps).
// ---------------------------------------------------------------------------
__global__ void __launch_bounds__(TPB, 1)
scan_kernel(const float* __restrict__ x,
            const float* __restrict__ S,
            const float* __restrict__ U,
            const float* __restrict__ A,
            float* __restrict__ out)
{
    extern __shared__ float sm[];
    const int tid = threadIdx.x;
    const int b0  = blockIdx.x * 4;

    // ---------------- stage S', A^T, (u2, k') ----------------
    for (int idx = tid; idx < NP * 16; idx += TPB) {
        int p = idx >> 4, k = idx & 15;
        sm[OFF_SQ + (k >> 2) * 3200 + (p << 2) + (k & 3)] = TWO_L2E * S[idx];
        sm[OFF_AT + k * 804 + p] = A[idx];
    }
    for (int p = tid; p < NP; p += TPB) {
        float acc = 0.0f;
#pragma unroll
        for (int k = 0; k < 16; k++) { float v = S[p * 16 + k]; acc = fmaf(v, v, acc); }
        float uv = U[p];
        sm[OFF_UK + 2 * p]     = TWO_L2E * uv;
        sm[OFF_UK + 2 * p + 1] = L2E * fmaf(uv, uv, acc);
    }
    if (tid < 32) {
        sm[OFF_GATE + tid] = g_gate[((size_t)(b0 + (tid >> 3)) * T_) * 8 + (tid & 7)];
        if (tid < 4) sm[OFF_XB + tid] = x[(size_t)(b0 + tid) * T_];
    }
    __syncthreads();

    const int b    = tid & 3;    // phase A batch
    const int pp   = tid >> 2;   // phase A dpair lane (0..127)
    const int nn   = tid & 15;   // phase B output dim
    const int j    = tid >> 4;   // phase B chunk lane (0..31)
    const int lane = tid & 31;
    const int wrp  = tid >> 5;

    const ulonglong2* Sq2 = (const ulonglong2*)(sm + OFF_SQ);
    const ulonglong2* At2 = (const ulonglong2*)(sm + OFF_AT + nn * 804);
    const ulonglong2* Wb2 = (const ulonglong2*)(sm + OFF_W);

    // -------- A register cache: 6 chunks per thread, static across t --------
    ulonglong2 Ac[6];
#pragma unroll
    for (int i = 0; i < 6; i++) Ac[i] = At2[j + 32 * i];

    // packed state (8 x f32x2); xv = raw x_t; hs = (-h', 0) dot seed
    u64 s0 = 0, s1 = 0, s2 = 0, s3 = 0, s4 = 0, s5 = 0, s6 = 0, s7 = 0;
    float xv = sm[OFF_XB + b];
    u64 hs = pk2(-L2E * xv * xv, 0.0f);

    for (int t = 0; t < T_; t++) {
        const int par = t & 1;

        // next-step gate/x loads (committed after bar1, consumed at step end)
        float gpre = 0.f, xpre = 0.f;
        const bool pf = (tid < 32) && (t + 1 < T_);
        if (pf) {
            gpre = g_gate[((size_t)(b0 + (tid >> 3)) * T_ + (t + 1)) * 8 + (tid & 7)];
            if (tid < 4) xpre = x[(size_t)(b0 + tid) * T_ + (t + 1)];
        }

        // ---------------- phase A: pairs (2dp, 2dp+1) ----------------
        {
            const float* gsh = sm + OFF_GATE + par * 32 + b * 8;

            auto dpair = [&](int dp, int ci) {
                const int p0 = 2 * dp;
                ulonglong2 q0a = Sq2[p0],        q0b = Sq2[p0 + 1];
                ulonglong2 q1a = Sq2[800 + p0],  q1b = Sq2[801 + p0];
                ulonglong2 q2a = Sq2[1600 + p0], q2b = Sq2[1601 + p0];
                ulonglong2 q3a = Sq2[2400 + p0], q3b = Sq2[2401 + p0];
                float4 uk4 = *(const float4*)(sm + OFF_UK + 4 * dp);
                float g = gsh[ci];

                u64 da = fma2(q0a.x, s0, hs);
                da = fma2(q0a.y, s1, da);
                da = fma2(q1a.x, s2, da);
                da = fma2(q1a.y, s3, da);
                u64 db = mul2(q2a.x, s4);
                db = fma2(q2a.y, s5, db);
                db = fma2(q3a.x, s6, db);
                db = fma2(q3a.y, s7, db);
                float2 fa = upk(da), fb = upk(db);
                float e0 = fmaf(xv, uk4.x, (fa.x + fa.y) + (fb.x + fb.y)) - uk4.y;

                u64 dc = fma2(q0b.x, s0, hs);
                dc = fma2(q0b.y, s1, dc);
                dc = fma2(q1b.x, s2, dc);
                dc = fma2(q1b.y, s3, dc);
                u64 dd = mul2(q2b.x, s4);
                dd = fma2(q2b.y, s5, dd);
                dd = fma2(q3b.x, s6, dd);
                dd = fma2(q3b.y, s7, dd);
                float2 fc = upk(dc), fd = upk(dd);
                float e1 = fmaf(xv, uk4.z, (fc.x + fc.y) + (fd.x + fd.y)) - uk4.w;

                *(float2*)(sm + OFF_W + b * 808 + p0) =
                    make_float2(g * ex2f(e0), g * ex2f(e1));
            };
#pragma unroll
            for (int i = 0; i < 3; i++) {
                int dp = pp + 128 * i;
                dpair(dp, (unsigned)dp / 50u);
            }
            // tail: 32 single pairs 768..799 on lanes pp>=96 (half a dpair each)
            if (pp >= 96) {
                const int p = 672 + pp;          // 768..799, cell 7
                ulonglong2 q0 = Sq2[p];
                ulonglong2 q1 = Sq2[800 + p];
                ulonglong2 q2 = Sq2[1600 + p];
                ulonglong2 q3 = Sq2[2400 + p];
                float2 uk2 = *(const float2*)(sm + OFF_UK + 2 * p);
                float g = gsh[7];
                u64 da = fma2(q0.x, s0, hs);
                da = fma2(q0.y, s1, da);
                da = fma2(q1.x, s2, da);
                da = fma2(q1.y, s3, da);
                u64 db = mul2(q2.x, s4);
                db = fma2(q2.y, s5, db);
                db = fma2(q3.x, s6, db);
                db = fma2(q3.y, s7, db);
                float2 fa = upk(da), fb = upk(db);
                float e0 = fmaf(xv, uk2.x, (fa.x + fa.y) + (fb.x + fb.y)) - uk2.y;
                sm[OFF_W + b * 808 + p] = g * ex2f(e0);
            }
        }
        __syncthreads();                             // bar 1

        // commit prefetched gate/x for t+1
        if (pf) {
            sm[OFF_GATE + (par ^ 1) * 32 + tid] = gpre;
            if (tid < 4) sm[OFF_XB + (par ^ 1) * 4 + tid] = xpre;
        }

        // ---------------- phase B: s_new[b][n] = sum_p w[b][p]*A[p][n] -------
        u64 c0 = 0, c1 = 0, c2 = 0, c3 = 0;
        auto chunkB = [&](int p4, ulonglong2 av) {
            ulonglong2 w0 = Wb2[p4];
            ulonglong2 w1 = Wb2[202 + p4];
            ulonglong2 w2 = Wb2[404 + p4];
            ulonglong2 w3 = Wb2[606 + p4];
            c0 = fma2(av.x, w0.x, c0); c0 = fma2(av.y, w0.y, c0);
            c1 = fma2(av.x, w1.x, c1); c1 = fma2(av.y, w1.y, c1);
            c2 = fma2(av.x, w2.x, c2); c2 = fma2(av.y, w2.y, c2);
            c3 = fma2(av.x, w3.x, c3); c3 = fma2(av.y, w3.y, c3);
        };
#pragma unroll
        for (int i = 0; i < 6; i++) chunkB(j + 32 * i, Ac[i]);
        // tail: chunks 192..199 as 16 half-chunks (2 pairs) on j<16 (warps 0-7)
        if (j < 16) {
            const int off = (192 + (j >> 1)) * 4 + (j & 1) * 2;   // float offset
            u64 ah = *(const u64*)(sm + OFF_AT + nn * 804 + off);
            u64 w0 = *(const u64*)(sm + OFF_W + off);
            u64 w1 = *(const u64*)(sm + OFF_W + 808 + off);
            u64 w2 = *(const u64*)(sm + OFF_W + 1616 + off);
            u64 w3 = *(const u64*)(sm + OFF_W + 2424 + off);
            c0 = fma2(ah, w0, c0);
            c1 = fma2(ah, w1, c1);
            c2 = fma2(ah, w2, c2);
            c3 = fma2(ah, w3, c3);
        }

        float2 f0 = upk(c0), f1 = upk(c1), f2 = upk(c2), f3 = upk(c3);
        float a0 = f0.x + f0.y, a1 = f1.x + f1.y, a2 = f2.x + f2.y, a3 = f3.x + f3.y;
        a0 += __shfl_xor_sync(0xffffffffu, a0, 16);
        a1 += __shfl_xor_sync(0xffffffffu, a1, 16);
        a2 += __shfl_xor_sync(0xffffffffu, a2, 16);
        a3 += __shfl_xor_sync(0xffffffffu, a3, 16);
        if (lane < 16) {
            sm[OFF_RED +       wrp * 16 + lane] = a0;
            sm[OFF_RED + 256 + wrp * 16 + lane] = a1;
            sm[OFF_RED + 512 + wrp * 16 + lane] = a2;
            sm[OFF_RED + 768 + wrp * 16 + lane] = a3;
        }
        __syncthreads();                             // bar 2

        // ---------------- final reduce + output (256 threads, 4+shfl) --------
        if (tid < 256) {
            const int bb = tid >> 6, n2 = (tid >> 2) & 15, g = tid & 3;
            const float* r = sm + OFF_RED + bb * 256 + g * 16 + n2;
            float v = (r[0] + r[64]) + (r[128] + r[192]);   // warps g, g+4, g+8, g+12
            v += __shfl_xor_sync(0xffffffffu, v, 1);
            v += __shfl_xor_sync(0xffffffffu, v, 2);
            if (g == 0) {
                sm[OFF_ST + bb * 20 + n2] = v;
                if (n2 == 15) out[(size_t)(b0 + bb) * T_ + t] = v;
            }
        }
        __syncthreads();                             // bar 3

        // reload packed state; recompute h' locally
        {
            const ulonglong2* st2 = (const ulonglong2*)(sm + OFF_ST + b * 20);
            ulonglong2 u0 = st2[0], u1 = st2[1], u2 = st2[2], u3 = st2[3];
            s0 = u0.x; s1 = u0.y; s2 = u1.x; s3 = u1.y;
            s4 = u2.x; s5 = u2.y; s6 = u3.x; s7 = u3.y;
            xv = sm[OFF_XB + (par ^ 1) * 4 + b];
            u64 acc = mul2(s0, s0);
            acc = fma2(s1, s1, acc);
            acc = fma2(s2, s2, acc);
            acc = fma2(s3, s3, acc);
            acc = fma2(s4, s4, acc);
            acc = fma2(s5, s5, acc);
            acc = fma2(s6, s6, acc);
            acc = fma2(s7, s7, acc);
            float2 fs = upk(acc);
            float hv = fmaf(xv, xv, fs.x + fs.y);
            hs = pk2(-L2E * hv, 0.0f);
        }
    }
}

// ---------------------------------------------------------------------------
extern "C" void kernel_launch(void* const* d_in, const int* in_sizes, int n_in,
                              void* d_out, int out_size)
{
    const float* x  = (const float*)d_in[0];
    const float* S  = (const float*)d_in[1];
    const float* U  = (const float*)d_in[2];
    const float* A  = (const float*)d_in[3];
    const float* W1 = (const float*)d_in[4];
    const float* b1 = (const float*)d_in[5];
    const float* W2 = (const float*)d_in[6];
    const float* b2 = (const float*)d_in[7];
    float* out = (float*)d_out;

    cudaFuncSetAttribute(scan_kernel,
                         cudaFuncAttributeMaxDynamicSharedMemorySize, SMEM_BYTES);

    gate_kernel<<<(B_ * T_ + 255) / 256, 256>>>(x, W1, b1, W2, b2);
    scan_kernel<<<NBLK, TPB, SMEM_BYTES>>>(x, S, U, A, out);
}

// round 11
// speedup vs baseline: 1.0720x; 1.0245x over previous
#include <cuda_runtime.h>
#include <cuda_bf16.h>
#include <cstdint>
#include <cstddef>

#define B_   512
#define T_   2048
#define NP   800          // C*M pairs
#define TPB  512
#define NBLK 128          // B_/4, 4 batches per block

#define L2E     1.4426950408889634f
#define TWO_L2E 2.8853900817779268f

// ---- shared layout (float offsets) ----
#define OFF_SQ   0        // Sq[4 quad][800][4] : S quads transposed, *2*log2e (12800 f)
#define OFF_AT   12800    // float at[16][804]  : A transposed, padded         (12864 f)
#define OFF_UK   25664    // float2 uk[800]     : (2*l2e*U, l2e*(|S|^2+U^2))   ( 1600 f)
#define OFF_W    27264    // float w[4][808]    : stride 808 -> conflict-free  ( 3232 f)
#define OFF_RED  30496    // float red[4][16][16]                              ( 1024 f)
#define OFF_ST   31520    // float st[4][20]                                   (   80 f)
#define OFF_GATE 31600    // float gate[2][4][8]                               (   64 f)
#define OFF_XB   31664    // float xb[2][4]                                    (    8 f)
#define SMEM_FLOATS 31672
#define SMEM_BYTES  (SMEM_FLOATS * 4)

typedef unsigned long long u64;

__device__ float g_gate[(size_t)B_ * T_ * 8];

__device__ __forceinline__ float ex2f(float a)
{
    float r;
    asm("ex2.approx.ftz.f32 %0, %1;" : "=f"(r) : "f"(a));
    return r;
}
__device__ __forceinline__ u64 fma2(u64 b, u64 c, u64 a)   // b*c + a
{
    u64 d;
    asm("fma.rn.f32x2 %0, %1, %2, %3;" : "=l"(d) : "l"(b), "l"(c), "l"(a));
    return d;
}
__device__ __forceinline__ u64 mul2(u64 a, u64 b)
{
    u64 d;
    asm("mul.rn.f32x2 %0, %1, %2;" : "=l"(d) : "l"(a), "l"(b));
    return d;
}
__device__ __forceinline__ float2 upk(u64 a)
{
    float2 f;
    asm("mov.b64 {%0, %1}, %2;" : "=f"(f.x), "=f"(f.y) : "l"(a));
    return f;
}
__device__ __forceinline__ u64 pk2(float lo, float hi)
{
    u64 d;
    asm("mov.b64 %0, {%1, %2};" : "=l"(d) : "f"(lo), "f"(hi));
    return d;
}

// ---------------------------------------------------------------------------
// Kernel 1: gate[b,t,:] = softmax(relu(x*W1+b1) @ W2 + b2). One thread per (b,t).
// ---------------------------------------------------------------------------
__global__ void gate_kernel(const float* __restrict__ x,
                            const float* __restrict__ W1,
                            const float* __restrict__ b1,
                            const float* __restrict__ W2,
                            const float* __restrict__ b2)
{
    int idx = blockIdx.x * blockDim.x + threadIdx.x;
    if (idx >= B_ * T_) return;
    float xv = x[idx];

    float lg[8];
#pragma unroll
    for (int c = 0; c < 8; c++) lg[c] = __ldg(&b2[c]);
#pragma unroll
    for (int jj = 0; jj < 16; jj++) {
        float h = fmaxf(fmaf(xv, __ldg(&W1[jj]), __ldg(&b1[jj])), 0.0f);
#pragma unroll
        for (int c = 0; c < 8; c++)
            lg[c] = fmaf(h, __ldg(&W2[jj * 8 + c]), lg[c]);
    }
    float m = lg[0];
#pragma unroll
    for (int c = 1; c < 8; c++) m = fmaxf(m, lg[c]);
    float e[8], ssum = 0.0f;
#pragma unroll
    for (int c = 0; c < 8; c++) { e[c] = __expf(lg[c] - m); ssum += e[c]; }
    float inv = 1.0f / ssum;
#pragma unroll
    for (int c = 0; c < 8; c++) g_gate[(size_t)idx * 8 + c] = e[c] * inv;
}

// ---------------------------------------------------------------------------
// Kernel 2: recurrent scan. 128 blocks x 512 threads, 4 batches per block.
// R6 base with an instruction diet in phase A:
//   - ONE 9-deep fma2 chain per pair (was 2 chains + 3-FADD combine)
//   - uk folded into the chain seed: fma2((u2,k'), (xv,-1), (-h',0))
//     lanes -> (u2*xv - h', -k'); final lane-add gives the full exponent.
// ---------------------------------------------------------------------------
__global__ void __launch_bounds__(TPB, 1)
scan_kernel(const float* __restrict__ x,
            const float* __restrict__ S,
            const float* __restrict__ U,
            const float* __restrict__ A,
            float* __restrict__ out)
{
    extern __shared__ float sm[];
    const int tid = threadIdx.x;
    const int b0  = blockIdx.x * 4;

    // ---------------- stage S', A^T, (u2, k') ----------------
    for (int idx = tid; idx < NP * 16; idx += TPB) {
        int p = idx >> 4, k = idx & 15;
        sm[OFF_SQ + (k >> 2) * 3200 + (p << 2) + (k & 3)] = TWO_L2E * S[idx];
        sm[OFF_AT + k * 804 + p] = A[idx];
    }
    for (int p = tid; p < NP; p += TPB) {
        float acc = 0.0f;
#pragma unroll
        for (int k = 0; k < 16; k++) { float v = S[p * 16 + k]; acc = fmaf(v, v, acc); }
        float uv = U[p];
        sm[OFF_UK + 2 * p]     = TWO_L2E * uv;
        sm[OFF_UK + 2 * p + 1] = L2E * fmaf(uv, uv, acc);
    }
    if (tid < 32) {
        sm[OFF_GATE + tid] = g_gate[((size_t)(b0 + (tid >> 3)) * T_) * 8 + (tid & 7)];
        if (tid < 4) sm[OFF_XB + tid] = x[(size_t)(b0 + tid) * T_];
    }
    __syncthreads();

    const int b    = tid & 3;    // phase A batch
    const int pp   = tid >> 2;   // phase A dpair lane (0..127)
    const int nn   = tid & 15;   // phase B output dim
    const int j    = tid >> 4;   // phase B chunk lane (0..31)
    const int lane = tid & 31;
    const int wrp  = tid >> 5;

    const ulonglong2* Sq2 = (const ulonglong2*)(sm + OFF_SQ);
    const ulonglong2* At2 = (const ulonglong2*)(sm + OFF_AT + nn * 804);
    const ulonglong2* Wb2 = (const ulonglong2*)(sm + OFF_W);

    // -------- A register cache: 6 chunks per thread, static across t --------
    ulonglong2 Ac[6];
#pragma unroll
    for (int i = 0; i < 6; i++) Ac[i] = At2[j + 32 * i];

    // packed state (8 x f32x2); xv = raw x_t
    // hs = (-h', 0) seed; xp = (xv, -1) uk-fold multiplier
    u64 s0 = 0, s1 = 0, s2 = 0, s3 = 0, s4 = 0, s5 = 0, s6 = 0, s7 = 0;
    float xv = sm[OFF_XB + b];
    u64 hs = pk2(-L2E * xv * xv, 0.0f);
    u64 xp = pk2(xv, -1.0f);

    for (int t = 0; t < T_; t++) {
        const int par = t & 1;

        // next-step gate/x loads (committed after bar1, consumed at step end)
        float gpre = 0.f, xpre = 0.f;
        const bool pf = (tid < 32) && (t + 1 < T_);
        if (pf) {
            gpre = g_gate[((size_t)(b0 + (tid >> 3)) * T_ + (t + 1)) * 8 + (tid & 7)];
            if (tid < 4) xpre = x[(size_t)(b0 + tid) * T_ + (t + 1)];
        }

        // ---------------- phase A: pairs (2dp, 2dp+1) ----------------
        {
            const float* gsh = sm + OFF_GATE + par * 32 + b * 8;

            auto dpair = [&](int dp, int ci) {
                const int p0 = 2 * dp;
                ulonglong2 q0a = Sq2[p0],        q0b = Sq2[p0 + 1];
                ulonglong2 q1a = Sq2[800 + p0],  q1b = Sq2[801 + p0];
                ulonglong2 q2a = Sq2[1600 + p0], q2b = Sq2[1601 + p0];
                ulonglong2 q3a = Sq2[2400 + p0], q3b = Sq2[2401 + p0];
                ulonglong2 ukp = *(const ulonglong2*)(sm + OFF_UK + 4 * dp);
                float g = gsh[ci];

                u64 da = fma2(ukp.x, xp, hs);     // (u2*xv - h', -k')
                da = fma2(q0a.x, s0, da);
                da = fma2(q0a.y, s1, da);
                da = fma2(q1a.x, s2, da);
                da = fma2(q1a.y, s3, da);
                da = fma2(q2a.x, s4, da);
                da = fma2(q2a.y, s5, da);
                da = fma2(q3a.x, s6, da);
                da = fma2(q3a.y, s7, da);
                float2 fa = upk(da);
                float e0 = fa.x + fa.y;

                u64 db = fma2(ukp.y, xp, hs);
                db = fma2(q0b.x, s0, db);
                db = fma2(q0b.y, s1, db);
                db = fma2(q1b.x, s2, db);
                db = fma2(q1b.y, s3, db);
                db = fma2(q2b.x, s4, db);
                db = fma2(q2b.y, s5, db);
                db = fma2(q3b.x, s6, db);
                db = fma2(q3b.y, s7, db);
                float2 fb = upk(db);
                float e1 = fb.x + fb.y;

                *(float2*)(sm + OFF_W + b * 808 + p0) =
                    make_float2(g * ex2f(e0), g * ex2f(e1));
            };
#pragma unroll
            for (int i = 0; i < 3; i++) {
                int dp = pp + 128 * i;
                dpair(dp, (unsigned)dp / 50u);
            }
            if (pp >= 112) dpair(272 + pp, 7);   // dp 384..399 -> pairs 768..799
        }
        __syncthreads();                             // bar 1

        // commit prefetched gate/x for t+1
        if (pf) {
            sm[OFF_GATE + (par ^ 1) * 32 + tid] = gpre;
            if (tid < 4) sm[OFF_XB + (par ^ 1) * 4 + tid] = xpre;
        }

        // ---------------- phase B: s_new[b][n] = sum_p w[b][p]*A[p][n] -------
        u64 c0 = 0, c1 = 0, c2 = 0, c3 = 0;
        auto chunkB = [&](int p4, ulonglong2 av) {
            ulonglong2 w0 = Wb2[p4];
            ulonglong2 w1 = Wb2[202 + p4];
            ulonglong2 w2 = Wb2[404 + p4];
            ulonglong2 w3 = Wb2[606 + p4];
            c0 = fma2(av.x, w0.x, c0); c0 = fma2(av.y, w0.y, c0);
            c1 = fma2(av.x, w1.x, c1); c1 = fma2(av.y, w1.y, c1);
            c2 = fma2(av.x, w2.x, c2); c2 = fma2(av.y, w2.y, c2);
            c3 = fma2(av.x, w3.x, c3); c3 = fma2(av.y, w3.y, c3);
        };
#pragma unroll
        for (int i = 0; i < 6; i++) chunkB(j + 32 * i, Ac[i]);
        if (j >= 24) chunkB(168 + j, At2[168 + j]);  // tail chunks 192..199

        float2 f0 = upk(c0), f1 = upk(c1), f2 = upk(c2), f3 = upk(c3);
        float a0 = f0.x + f0.y, a1 = f1.x + f1.y, a2 = f2.x + f2.y, a3 = f3.x + f3.y;
        a0 += __shfl_xor_sync(0xffffffffu, a0, 16);
        a1 += __shfl_xor_sync(0xffffffffu, a1, 16);
        a2 += __shfl_xor_sync(0xffffffffu, a2, 16);
        a3 += __shfl_xor_sync(0xffffffffu, a3, 16);
        if (lane < 16) {
            sm[OFF_RED +       wrp * 16 + lane] = a0;
            sm[OFF_RED + 256 + wrp * 16 + lane] = a1;
            sm[OFF_RED + 512 + wrp * 16 + lane] = a2;
            sm[OFF_RED + 768 + wrp * 16 + lane] = a3;
        }
        __syncthreads();                             // bar 2

        // ---------------- final reduce + output (256 threads, 4+shfl) --------
        if (tid < 256) {
            const int bb = tid >> 6, n2 = (tid >> 2) & 15, g = tid & 3;
            const float* r = sm + OFF_RED + bb * 256 + g * 16 + n2;
            float v = (r[0] + r[64]) + (r[128] + r[192]);   // warps g, g+4, g+8, g+12
            v += __shfl_xor_sync(0xffffffffu, v, 1);
            v += __shfl_xor_sync(0xffffffffu, v, 2);
            if (g == 0) {
                sm[OFF_ST + bb * 20 + n2] = v;
                if (n2 == 15) out[(size_t)(b0 + bb) * T_ + t] = v;
            }
        }
        __syncthreads();                             // bar 3

        // reload packed state; recompute h', xp locally
        {
            const ulonglong2* st2 = (const ulonglong2*)(sm + OFF_ST + b * 20);
            ulonglong2 u0 = st2[0], u1 = st2[1], u2 = st2[2], u3 = st2[3];
            s0 = u0.x; s1 = u0.y; s2 = u1.x; s3 = u1.y;
            s4 = u2.x; s5 = u2.y; s6 = u3.x; s7 = u3.y;
            xv = sm[OFF_XB + (par ^ 1) * 4 + b];
            u64 acc = mul2(s0, s0);
            acc = fma2(s1, s1, acc);
            acc = fma2(s2, s2, acc);
            acc = fma2(s3, s3, acc);
            acc = fma2(s4, s4, acc);
            acc = fma2(s5, s5, acc);
            acc = fma2(s6, s6, acc);
            acc = fma2(s7, s7, acc);
            float2 fs = upk(acc);
            float hv = fmaf(xv, xv, fs.x + fs.y);
            hs = pk2(-L2E * hv, 0.0f);
            xp = pk2(xv, -1.0f);
        }
    }
}

// ---------------------------------------------------------------------------
extern "C" void kernel_launch(void* const* d_in, const int* in_sizes, int n_in,
                              void* d_out, int out_size)
{
    const float* x  = (const float*)d_in[0];
    const float* S  = (const float*)d_in[1];
    const float* U  = (const float*)d_in[2];
    const float* A  = (const float*)d_in[3];
    const float* W1 = (const float*)d_in[4];
    const float* b1 = (const float*)d_in[5];
    const float* W2 = (const float*)d_in[6];
    const float* b2 = (const float*)d_in[7];
    float* out = (float*)d_out;

    cudaFuncSetAttribute(scan_kernel,
                         cudaFuncAttributeMaxDynamicSharedMemorySize, SMEM_BYTES);

    gate_kernel<<<(B_ * T_ + 255) / 256, 256>>>(x, W1, b1, W2, b2);
    scan_kernel<<<NBLK, TPB, SMEM_BYTES>>>(x, S, U, A, out);
}